// round 14
// baseline (speedup 1.0000x reference)
#include <cuda_runtime.h>
#include <math.h>

#define T_ 200
#define N_ 256
#define H_ 128
#define G_ 512   // 4*H
#define V_ 50000

#define TB 10          // time-block size (divides 200, even)
#define NBLK (T_/TB)   // 20 blocks
#define NB 4           // sequences per cluster
#define NCLUST (N_/NB) // 64 clusters -> 128 CTAs
#define HD 64          // h-dims owned per CTA

typedef unsigned long long ull;

// Scratch (static device globals — allocation-free per harness rules)
__device__ float g_wx[(size_t)T_ * N_ * G_];    // 104.8 MB
__device__ float g_hhist[(size_t)T_ * N_ * H_]; // 26.2 MB
__device__ float g_chist[(size_t)T_ * N_ * H_]; // 26.2 MB
__device__ float g_hmean[N_ * H_];

// fast transcendentals (error ~1e-6, far under the 1e-3 gate)
__device__ __forceinline__ float fsig(float x) {
    return __fdividef(1.0f, 1.0f + __expf(-x));
}
__device__ __forceinline__ float ftanh(float x) {
    float a = fabsf(x);
    float e = __expf(-2.0f * a);
    float r = __fdividef(1.0f - e, 1.0f + e);
    return copysignf(r, x);
}

// ---- packed f32x2 helpers ----
__device__ __forceinline__ ull pk2(float x, float y) {
    ull r; asm("mov.b64 %0,{%1,%2};" : "=l"(r) : "f"(x), "f"(y)); return r;
}
__device__ __forceinline__ ull f2fma(ull a, ull b, ull c) {
    ull d; asm("fma.rn.f32x2 %0,%1,%2,%3;" : "=l"(d) : "l"(a), "l"(b), "l"(c)); return d;
}
__device__ __forceinline__ float2 up2(ull v) {
    float lo, hi; asm("mov.b64 {%0,%1},%2;" : "=f"(lo), "=f"(hi) : "l"(v));
    float2 r; r.x = lo; r.y = hi; return r;
}
__device__ __forceinline__ unsigned smem_u32(const void* p) {
    unsigned a;
    asm("{ .reg .u64 t; cvta.to.shared.u64 t, %1; cvt.u32.u64 %0, t; }" : "=r"(a) : "l"(p));
    return a;
}
__device__ __forceinline__ unsigned mapa_peer(unsigned addr, unsigned peer_rank) {
    unsigned pa;
    asm("mapa.shared::cluster.u32 %0, %1, %2;" : "=r"(pa) : "r"(addr), "r"(peer_rank));
    return pa;
}
#define CLUSTER_SYNC() do { \
    asm volatile("barrier.cluster.arrive.aligned;" ::: "memory"); \
    asm volatile("barrier.cluster.wait.aligned;"   ::: "memory"); \
} while (0)

// mbarrier primitives (tx-only protocol: init count=1, tid0 expect_tx arrives)
#define MBAR_INIT(addr, cnt) \
    asm volatile("mbarrier.init.shared.b64 [%0], %1;" :: "r"(addr), "r"(cnt) : "memory")
#define MBAR_EXPECT_TX(addr, bytes) \
    asm volatile("mbarrier.arrive.expect_tx.shared.b64 _, [%0], %1;" :: "r"(addr), "r"(bytes) : "memory")
// acquire at CLUSTER scope: orders peer st.async data before our reads
#define MBAR_WAIT_PARITY_CLUSTER(addr, par) do { \
    unsigned _m = (addr), _p = (par), _done; \
    asm volatile( \
        "{\n\t.reg .pred p;\n\t" \
        "mbarrier.try_wait.parity.acquire.cluster.shared::cta.b64 p, [%1], %2;\n\t" \
        "selp.b32 %0, 1, 0, p;\n\t}" : "=r"(_done) : "r"(_m), "r"(_p) : "memory"); \
    if (!_done) { \
        asm volatile( \
            "{\n\t.reg .pred P1;\n\t" \
            "WL_%=:\n\t" \
            "mbarrier.try_wait.parity.acquire.cluster.shared::cta.b64 P1, [%0], %1, 0x989680;\n\t" \
            "@P1 bra.uni WD_%=;\n\t" \
            "bra.uni WL_%=;\n\t" \
            "WD_%=:\n\t}" :: "r"(_m), "r"(_p) : "memory"); \
    } \
} while (0)
// paired async store to peer smem, tx-counted on peer's mbarrier
__device__ __forceinline__ void stasync_peer64(unsigned paddr, ull v, unsigned pbar) {
    asm volatile(
        "st.async.weak.shared::cluster.mbarrier::complete_tx::bytes.b64 [%0], %1, [%2];"
        :: "r"(paddr), "l"(v), "r"(pbar) : "memory");
}

// ---------------------------------------------------------------------------
// Kernel 1: Wx = emb[seq] @ W + b.  64x64 tile, 4x4 register tile, k-quad
// vectorized As (measured 184-185us — best configuration).
// ---------------------------------------------------------------------------
__global__ void __launch_bounds__(256) wx_kernel(const int* __restrict__ seq,
                                                 const float* __restrict__ emb,
                                                 const float* __restrict__ W,
                                                 const float* __restrict__ b)
{
    extern __shared__ float sm[];
    float* As = sm;                 // [64][132]
    float* Bs = sm + 64 * 132;      // [128][64]
    int*   ridx = (int*)(Bs + 128 * 64);

    const int tid = threadIdx.x;
    const int bc = blockIdx.x;
    const int br = blockIdx.y;

    if (tid < 64) ridx[tid] = seq[br * 64 + tid];
    __syncthreads();

    for (int p = tid; p < 64 * 32; p += 256) {
        int r = p >> 5, kq = p & 31;
        float4 v = *(const float4*)(emb + (size_t)ridx[r] * H_ + kq * 4);
        float* dst = As + r * 132 + kq * 4;
        dst[0] = v.x; dst[1] = v.y; dst[2] = v.z; dst[3] = v.w;
    }
    for (int p = tid; p < 128 * 16; p += 256) {
        int k = p >> 4, cq = p & 15;
        *(float4*)(Bs + k * 64 + cq * 4) = *(const float4*)(W + k * G_ + bc * 64 + cq * 4);
    }
    __syncthreads();

    const int ty = tid >> 4, tx = tid & 15;
    const int r0 = ty * 4, c0 = tx * 4;
    ull a01[4], a23[4];
    #pragma unroll
    for (int i = 0; i < 4; i++) { a01[i] = 0ull; a23[i] = 0ull; }

    #pragma unroll 4
    for (int k4 = 0; k4 < 32; ++k4) {
        const int kb = k4 * 4;
        float a[4][4];
        #pragma unroll
        for (int i = 0; i < 4; i++)
            *(float4*)a[i] = *(const float4*)(As + (r0 + i) * 132 + kb);
        #pragma unroll
        for (int kk = 0; kk < 4; ++kk) {
            ulonglong2 bv = *(const ulonglong2*)(Bs + (kb + kk) * 64 + c0);
            #pragma unroll
            for (int i = 0; i < 4; i++) {
                ull ap = pk2(a[i][kk], a[i][kk]);
                a01[i] = f2fma(ap, bv.x, a01[i]);
                a23[i] = f2fma(ap, bv.y, a23[i]);
            }
        }
    }

    float4 bias = *(const float4*)(b + bc * 64 + c0);
    #pragma unroll
    for (int i = 0; i < 4; i++) {
        int row = br * 64 + r0 + i;
        float2 p01 = up2(a01[i]), p23 = up2(a23[i]);
        float4 o;
        o.x = p01.x + bias.x;
        o.y = p01.y + bias.y;
        o.z = p23.x + bias.z;
        o.w = p23.y + bias.w;
        __stcs((float4*)(g_wx + (size_t)row * G_ + bc * 64 + c0), o);
    }
}

// ---------------------------------------------------------------------------
// Kernel 2: recurrence v11 — group-staggered pipeline. Seqs {0,1}=X, {2,3}=Y,
// each with its own double-buffered tx-only mbar. The X(t+1) publish has the
// whole Y half-step between it and waitX(t+1), hiding st.async flight + skew.
// Ring/P interleaved (h,c) ull so taps are 1 LDS.64 + 1 f2fma. Peer publish
// via paired st.async.b64.
// ---------------------------------------------------------------------------
__global__ void __launch_bounds__(256, 1) __cluster_dims__(2, 1, 1)
rec9_kernel(const float* __restrict__ mask,
            const float* __restrict__ topo,
            const float* __restrict__ U)
{
    extern __shared__ float sm[];
    // sm[0..8): 4 mbarriers (8B each): X0, X1, Y0, Y1
    float* topoT = sm + 8;                   // [4][200][12] = 9600
    float* P2    = topoT + 4 * 200 * 12;     // [TB][4][64] ull (h,c) = 5120 fl
    float* ring2 = P2 + 2 * TB * NB * HD;    // [TB][4][64] ull (h,c) = 5120 fl
    float* hsumP = ring2 + 2 * TB * NB * HD; // [2][4][128] = 1024 fl
    float* glX   = hsumP + 2 * NB * H_;      // [2 seq][4 gate][64] = 512
    float* glY   = glX + 512;                // 512
    float* smask = glY + 512;                // [TB][4]

    ull* P2u    = (ull*)P2;
    ull* ring2u = (ull*)ring2;

    const int tid  = threadIdx.x;
    const int wid  = tid >> 5;
    const int lane = tid & 31;
    const unsigned rank = blockIdx.x & 1;
    const int clu = blockIdx.x >> 1;
    const int n0  = clu * NB;
    const int d0  = rank * HD;               // my dim base

    const int gg = tid >> 6, dl = tid & 63;
    const int gc = gg * 128 + d0 + dl;       // global gate column

    // ---- U column pre-packed into 64 ull register pairs (plain i order) ----
    ull u[H_ / 2];
    #pragma unroll
    for (int q = 0; q < H_ / 2; ++q)
        u[q] = pk2(U[(size_t)(2 * q) * G_ + gc], U[(size_t)(2 * q + 1) * G_ + gc]);

    // cell identity (threads < 128): group-seq ejg (0..1), dim ed (0..63)
    const int ejg = (tid >> 6) & 1;
    const int ed  = tid & 63;
    const unsigned peer = rank ^ 1;

    // mbarriers: tx-only (count=1), 512 tx bytes per group publish
    const unsigned barb = smem_u32(sm);
    if (tid == 0) {
        MBAR_INIT(barb,      1);  // X buf0
        MBAR_INIT(barb + 8,  1);  // X buf1
        MBAR_INIT(barb + 16, 1);  // Y buf0
        MBAR_INIT(barb + 24, 1);  // Y buf1
    }
    __syncthreads();
    CLUSTER_SYNC();   // peer bars initialized before any st.async targets them

    const unsigned hsum_base  = smem_u32(hsumP);
    const unsigned phsum_base = mapa_peer(hsum_base, peer);
    const unsigned pbarb      = mapa_peer(barb, peer);

    float haccX = 0.0f, lsumX = 0.0f, haccY = 0.0f, lsumY = 0.0f;
    float ac_cur0 = 0.0f, ac_cur1 = 0.0f;

    for (int k = 0; k < NBLK; ++k) {
        const int t0 = k * TB;
        const int plen = t0 + TB;

        // ---- topo prefix + mask (prior readers done at epilogue barrier) ----
        for (int r_ = wid; r_ < TB * NB; r_ += 8) {
            int tt = r_ / NB, j = r_ % NB;
            const float* src = topo + ((size_t)(t0 + tt) * N_ + (n0 + j)) * T_;
            for (int tp = lane; tp < plen; tp += 32)
                topoT[(j * 200 + tp) * 12 + tt] = __ldcs(src + tp);
        }
        if (tid < TB * NB) {
            int tt = tid >> 2, j = tid & 3;
            smask[tt * NB + j] = mask[(t0 + tt) * N_ + n0 + j];
        }
        __syncthreads();

        // ---- prologue: P2[tt][j][ed] = (ah, ac) from global history ----
        if (k == 0) {
            for (int i = tid; i < 2 * TB * NB * HD; i += 256) P2[i] = 0.0f;
        } else {
            const int j  = wid >> 1;
            const int hc = wid & 1;
            const float* hist = hc ? g_chist : g_hhist;
            const int dl2 = lane * 2;
            ull acc[5][2];
            #pragma unroll
            for (int pr = 0; pr < 5; pr++) { acc[pr][0] = 0ull; acc[pr][1] = 0ull; }
            #pragma unroll 4
            for (int tp = 0; tp < t0; ++tp) {
                float2 hv = *(const float2*)(hist + ((size_t)tp * N_ + n0 + j) * H_ + d0 + dl2);
                const float* tr = topoT + (j * 200 + tp) * 12;
                ulonglong2 wA = *(const ulonglong2*)(tr);
                ulonglong2 wB = *(const ulonglong2*)(tr + 4);
                ull        wC = *(const ull*)(tr + 8);
                ull h0 = pk2(hv.x, hv.x), h1 = pk2(hv.y, hv.y);
                acc[0][0] = f2fma(wA.x, h0, acc[0][0]); acc[0][1] = f2fma(wA.x, h1, acc[0][1]);
                acc[1][0] = f2fma(wA.y, h0, acc[1][0]); acc[1][1] = f2fma(wA.y, h1, acc[1][1]);
                acc[2][0] = f2fma(wB.x, h0, acc[2][0]); acc[2][1] = f2fma(wB.x, h1, acc[2][1]);
                acc[3][0] = f2fma(wB.y, h0, acc[3][0]); acc[3][1] = f2fma(wB.y, h1, acc[3][1]);
                acc[4][0] = f2fma(wC,   h0, acc[4][0]); acc[4][1] = f2fma(wC,   h1, acc[4][1]);
            }
            // interleaved store: h-warps write .x field, c-warps .y field
            #pragma unroll
            for (int pr = 0; pr < 5; pr++) {
                float2 a0 = up2(acc[pr][0]);   // dims dl2   at tt = 2pr, 2pr+1
                float2 a1 = up2(acc[pr][1]);   // dims dl2+1
                P2[(((2 * pr)     * NB + j) * HD + dl2)     * 2 + hc] = a0.x;
                P2[(((2 * pr + 1) * NB + j) * HD + dl2)     * 2 + hc] = a0.y;
                P2[(((2 * pr)     * NB + j) * HD + dl2 + 1) * 2 + hc] = a1.x;
                P2[(((2 * pr + 1) * NB + j) * HD + dl2 + 1) * 2 + hc] = a1.y;
            }
        }
        __syncthreads();

        // ---- block-start publish for t0 (buf 0), both groups ----
        if (tid < 128) {
            #pragma unroll
            for (int g = 0; g < 2; ++g) {
                int j = g * 2 + ejg;
                float2 aa = up2(P2u[(0 * NB + j) * HD + ed]);
                if (g == 0) ac_cur0 = aa.y; else ac_cur1 = aa.y;
                unsigned loff = (unsigned)(((0 * NB + j) * H_ + d0 + ed) * 4);
                asm volatile("st.shared.f32 [%0], %1;"
                             :: "r"(hsum_base + loff), "f"(aa.x) : "memory");
                float ahn = __shfl_down_sync(0xffffffffu, aa.x, 1);
                if ((ed & 1) == 0)
                    stasync_peer64(phsum_base + loff, pk2(aa.x, ahn),
                                   pbarb + (unsigned)(g * 16));
                if (tid == 0) MBAR_EXPECT_TX(barb + (unsigned)(g * 16), 512);
            }
        }

        // ---- sequential steps: X half then Y half ----
        for (int tt = 0; tt < TB; ++tt) {
            const int t = t0 + tt;
            const int buf = t & 1;
            const unsigned par = (unsigned)((t >> 1) & 1);

            // prefetch Wx for all 4 seqs (consumed after GEMVs)
            const float* wbase = g_wx + ((size_t)t * N_ + n0) * G_ + gc;
            float w0 = __ldcs(wbase);
            float w1 = __ldcs(wbase + G_);
            float w2 = __ldcs(wbase + 2 * G_);
            float w3 = __ldcs(wbase + 3 * G_);

            #pragma unroll
            for (int g = 0; g < 2; ++g) {
                const unsigned gbar  = barb  + (unsigned)(g * 16) + (unsigned)(buf * 8);
                const unsigned pgbar = pbarb + (unsigned)(g * 16) + (unsigned)(buf * 8);
                float* gl = g ? glY : glX;
                float wa = g ? w2 : w0;
                float wb = g ? w3 : w1;

                MBAR_WAIT_PARITY_CLUSTER(gbar, par);

                // GEMV: 2 seqs of this group, full 128 i's
                {
                    ull a0 = 0ull, a1 = 0ull;
                    const float* h0p = hsumP + (buf * NB + g * 2) * H_;
                    const float* h1p = h0p + H_;
                    #pragma unroll
                    for (int q4 = 0; q4 < 32; ++q4) {
                        ulonglong2 hh0 = *(const ulonglong2*)(h0p + q4 * 4);
                        ulonglong2 hh1 = *(const ulonglong2*)(h1p + q4 * 4);
                        ull ua = u[2 * q4], ub = u[2 * q4 + 1];
                        a0 = f2fma(hh0.x, ua, a0); a0 = f2fma(hh0.y, ub, a0);
                        a1 = f2fma(hh1.x, ua, a1); a1 = f2fma(hh1.y, ub, a1);
                    }
                    float2 p0 = up2(a0), p1 = up2(a1);
                    gl[(0 * 4 + gg) * 64 + dl] = p0.x + p0.y + wa;
                    gl[(1 * 4 + gg) * 64 + dl] = p1.x + p1.y + wb;
                }
                __syncthreads();

                // cell + next-step aggregation + publish (threads < 128)
                if (tid < 128) {
                    int j = g * 2 + ejg;
                    float m  = smask[tt * NB + j];
                    float ig = fsig(gl[(ejg * 4 + 0) * 64 + ed]);
                    float fg = fsig(gl[(ejg * 4 + 1) * 64 + ed]);
                    float og = fsig(gl[(ejg * 4 + 2) * 64 + ed]);
                    float gt = ftanh(gl[(ejg * 4 + 3) * 64 + ed]);
                    float accp = (g == 0) ? ac_cur0 : ac_cur1;
                    float c  = m * (fg * accp + ig * gt);
                    float h  = m * (og * ftanh(c));
                    ring2u[(tt * NB + j) * HD + ed] = pk2(h, c);
                    if (g == 0) { haccX += m * h; lsumX += m; }
                    else        { haccY += m * h; lsumY += m; }

                    if (tt + 1 < TB) {
                        ull pacc = P2u[((tt + 1) * NB + j) * HD + ed];
                        const float* tb2 = topoT + (j * 200 + t0) * 12 + (tt + 1);
                        for (int s = 0; s <= tt; ++s) {
                            float w = tb2[s * 12];
                            pacc = f2fma(pk2(w, w), ring2u[(s * NB + j) * HD + ed], pacc);
                        }
                        float2 aa = up2(pacc);
                        if (g == 0) ac_cur0 = aa.y; else ac_cur1 = aa.y;
                        const int nbuf = (t + 1) & 1;
                        unsigned loff = (unsigned)(((nbuf * NB + j) * H_ + d0 + ed) * 4);
                        asm volatile("st.shared.f32 [%0], %1;"
                                     :: "r"(hsum_base + loff), "f"(aa.x) : "memory");
                        float ahn = __shfl_down_sync(0xffffffffu, aa.x, 1);
                        if ((ed & 1) == 0)
                            stasync_peer64(phsum_base + loff, pk2(aa.x, ahn),
                                           pgbar ^ (unsigned)(buf * 8) ^ (unsigned)(nbuf * 8));
                        if (tid == 0)
                            MBAR_EXPECT_TX(gbar ^ (unsigned)(buf * 8) ^ (unsigned)(nbuf * 8), 512);
                    }
                }
            }
        }

        // ---- block epilogue: flush ring2 to global history (batched) ----
        for (int p = tid; p < TB * NB * HD; p += 256) {
            int s = p >> 8;                    // / (NB*HD)
            int rem = p & 255;
            int j = rem >> 6, d = rem & 63;
            float2 hc = up2(ring2u[p]);
            g_hhist[((size_t)(t0 + s) * N_ + n0 + j) * H_ + d0 + d] = hc.x;
            g_chist[((size_t)(t0 + s) * N_ + n0 + j) * H_ + d0 + d] = hc.y;
        }
        __syncthreads();   // flush visible + topoT/ring readers done before next block
    }

    if (tid < 128) {
        g_hmean[(n0 + ejg)     * H_ + d0 + ed] = haccX / lsumX;
        g_hmean[(n0 + 2 + ejg) * H_ + d0 + ed] = haccY / lsumY;
    }
    CLUSTER_SYNC();   // no CTA exits while peer st.async may be in flight
}

// ---------------------------------------------------------------------------
// Kernel 3: out = h_mean @ W_out + b_out   (4x4 tile, k-quad vectorized As)
// ---------------------------------------------------------------------------
__global__ void __launch_bounds__(256) out_kernel(const float* __restrict__ Wout,
                                                  const float* __restrict__ bout,
                                                  float* __restrict__ out)
{
    extern __shared__ float sm[];
    float* As = sm;                 // [64][132]
    float* Bs = sm + 64 * 132;      // [128][64]

    const int tid = threadIdx.x;
    const int bc = blockIdx.x;
    const int br = blockIdx.y;
    const int cbase = bc * 64;

    for (int p = tid; p < 64 * 32; p += 256) {
        int r = p >> 5, kq = p & 31;
        float4 v = *(const float4*)(g_hmean + (size_t)(br * 64 + r) * H_ + kq * 4);
        float* dst = As + r * 132 + kq * 4;
        dst[0] = v.x; dst[1] = v.y; dst[2] = v.z; dst[3] = v.w;
    }
    for (int p = tid; p < 128 * 16; p += 256) {
        int k = p >> 4, cq = p & 15;
        int c = cbase + cq * 4;
        float4 v = make_float4(0.f, 0.f, 0.f, 0.f);
        if (c < V_) v = *(const float4*)(Wout + (size_t)k * V_ + c);
        *(float4*)(Bs + k * 64 + cq * 4) = v;
    }
    __syncthreads();

    const int ty = tid >> 4, tx = tid & 15;
    const int r0 = ty * 4, c0 = tx * 4;
    ull a01[4], a23[4];
    #pragma unroll
    for (int i = 0; i < 4; i++) { a01[i] = 0ull; a23[i] = 0ull; }

    #pragma unroll 4
    for (int k4 = 0; k4 < 32; ++k4) {
        const int kb = k4 * 4;
        float a[4][4];
        #pragma unroll
        for (int i = 0; i < 4; i++)
            *(float4*)a[i] = *(const float4*)(As + (r0 + i) * 132 + kb);
        #pragma unroll
        for (int kk = 0; kk < 4; ++kk) {
            ulonglong2 bv = *(const ulonglong2*)(Bs + (kb + kk) * 64 + c0);
            #pragma unroll
            for (int i = 0; i < 4; i++) {
                ull ap = pk2(a[i][kk], a[i][kk]);
                a01[i] = f2fma(ap, bv.x, a01[i]);
                a23[i] = f2fma(ap, bv.y, a23[i]);
            }
        }
    }

    int c = cbase + c0;
    if (c < V_) {
        float4 bias = *(const float4*)(bout + c);
        #pragma unroll
        for (int i = 0; i < 4; i++) {
            int row = br * 64 + r0 + i;
            float2 p01 = up2(a01[i]), p23 = up2(a23[i]);
            float4 o;
            o.x = p01.x + bias.x;
            o.y = p01.y + bias.y;
            o.z = p23.x + bias.z;
            o.w = p23.y + bias.w;
            *(float4*)(out + (size_t)row * V_ + c) = o;
        }
    }
}

// ---------------------------------------------------------------------------
extern "C" void kernel_launch(void* const* d_in, const int* in_sizes, int n_in,
                              void* d_out, int out_size)
{
    const int*   seq  = (const int*)d_in[0];
    const float* mask = (const float*)d_in[1];
    const float* topo = (const float*)d_in[2];
    const float* W    = (const float*)d_in[3];
    const float* U    = (const float*)d_in[4];
    const float* b    = (const float*)d_in[5];
    const float* emb  = (const float*)d_in[6];
    const float* Wout = (const float*)d_in[7];
    const float* bout = (const float*)d_in[8];
    float* out = (float*)d_out;

    const int smem_gemm = (64 * 132 + 128 * 64 + 64) * 4;     // 66,816 B
    const int smem_rec  = (8 + 4 * 200 * 12 + 2 * TB * NB * HD * 2
                           + 2 * NB * H_ + 2 * 512 + TB * NB + 16) * 4;  // ~88 KB

    cudaFuncSetAttribute(wx_kernel,   cudaFuncAttributeMaxDynamicSharedMemorySize, smem_gemm);
    cudaFuncSetAttribute(out_kernel,  cudaFuncAttributeMaxDynamicSharedMemorySize, smem_gemm);
    cudaFuncSetAttribute(rec9_kernel, cudaFuncAttributeMaxDynamicSharedMemorySize, smem_rec);

    wx_kernel<<<dim3(G_ / 64, (T_ * N_) / 64), 256, smem_gemm>>>(seq, emb, W, b);
    rec9_kernel<<<2 * NCLUST, 256, smem_rec>>>(mask, topo, U);
    out_kernel<<<dim3((V_ + 63) / 64, N_ / 64), 256, smem_gemm>>>(Wout, bout, out);
}